// round 2
// baseline (speedup 1.0000x reference)
#include <cuda_runtime.h>

typedef unsigned long long ull;

#define B_      8
#define SQ_     16
#define H_      16
#define D_      128
#define CACHE_  8192
#define SKV_    16
#define TT      64      // keys per tile
#define KPAD    132     // padded floats per K row (conflict-free LDS.128)
#define NTHREADS 256
#define SCALE   0.08838834764831845f   // 1/sqrt(128)

__device__ __forceinline__ ull f2fma(ull a, ull b, ull c){
    ull d; asm("fma.rn.f32x2 %0, %1, %2, %3;" : "=l"(d) : "l"(a), "l"(b), "l"(c)); return d;
}
__device__ __forceinline__ ull f2mul(ull a, ull b){
    ull d; asm("mul.rn.f32x2 %0, %1, %2;" : "=l"(d) : "l"(a), "l"(b)); return d;
}
__device__ __forceinline__ ull pack2(float x, float y){
    ull d; asm("mov.b64 %0, {%1, %2};" : "=l"(d) : "f"(x), "f"(y)); return d;
}
__device__ __forceinline__ float2 unpack2(ull a){
    float2 r; asm("mov.b64 {%0, %1}, %2;" : "=f"(r.x), "=f"(r.y) : "l"(a)); return r;
}
__device__ __forceinline__ void cp16(void* dst, const void* src){
    unsigned sa = (unsigned)__cvta_generic_to_shared(dst);
    asm volatile("cp.async.cg.shared.global [%0], [%1], 16;" :: "r"(sa), "l"(src));
}

__global__ void __launch_bounds__(NTHREADS, 1)
attn_kernel(const float* __restrict__ qg, const float* __restrict__ kn,
            const float* __restrict__ vn, const float* __restrict__ kc,
            const float* __restrict__ vc, const int* __restrict__ sptr,
            float* __restrict__ outg)
{
    extern __shared__ float smem[];
    float* ks = smem;                 // [2][TT][KPAD]
    float* vs = smem + 2*TT*KPAD;     // [2][TT][D_]

    const int bh = blockIdx.x;
    const int b = bh / H_, h = bh % H_;
    const int start = sptr[0];
    const int ktot = start + SKV_;
    const int ntiles = (ktot + TT - 1) / TT;

    const int tid  = threadIdx.x;
    const int lane = tid & 31;
    const int wid  = tid >> 5;
    const int jl   = lane & 7;     // key sub-lane (8 keys per group)
    const int qsec = lane >> 3;    // d-section: 32 dims each
    const int q0   = wid * 2;      // 2 queries per warp

    // ---- Q in registers (loaded once): qr[qi][r] covers dims qsec*32 + 4r .. +3
    ulonglong2 qr[2][8];
    #pragma unroll
    for (int qi = 0; qi < 2; ++qi){
        const float* qp = qg + ((b*SQ_ + (q0+qi))*H_ + h)*D_ + qsec*32;
        #pragma unroll
        for (int r = 0; r < 8; ++r)
            qr[qi][r] = *reinterpret_cast<const ulonglong2*>(qp + 4*r);
    }

    auto load_tile = [&](int t, int buf){
        const int base = t * TT;
        float* kdst = ks + buf*TT*KPAD;
        float* vdst = vs + buf*TT*D_;
        #pragma unroll
        for (int i = 0; i < 8; ++i){
            int c   = tid + i*NTHREADS;      // 2048 16B-chunks per tensor
            int j   = c >> 5;                // key row within tile
            int col = (c & 31) << 2;         // float column
            int s = base + j;
            if (s >= ktot) s = ktot - 1;     // clamp: masked later, keeps data finite
            const float *srck, *srcv;
            if (s < start){
                int off = ((b*CACHE_ + s)*H_ + h)*D_ + col;
                srck = kc + off; srcv = vc + off;
            } else {
                int off = ((b*SKV_ + (s-start))*H_ + h)*D_ + col;
                srck = kn + off; srcv = vn + off;
            }
            cp16(kdst + j*KPAD + col, srck);
            cp16(vdst + j*D_   + col, srcv);
        }
        asm volatile("cp.async.commit_group;");
    };

    float m[2]    = {-1e30f, -1e30f};
    float lsum[2] = {0.f, 0.f};
    ull a01[2], a23[2];
    a01[0]=a01[1]=a23[0]=a23[1]=pack2(0.f, 0.f);

    load_tile(0, 0);

    for (int t = 0; t < ntiles; ++t){
        const int buf = t & 1;
        const bool more = (t+1 < ntiles);
        if (more) load_tile(t+1, buf^1);
        if (more) asm volatile("cp.async.wait_group 1;");
        else      asm volatile("cp.async.wait_group 0;");
        __syncthreads();

        const float* kb  = ks + buf*TT*KPAD;
        const float* vb  = vs + buf*TT*D_;
        const int   base = t * TT;

        // ---- QK^T scores: lane (qsec,jl) computes 32-dim partial dots for 8 keys
        float p[2][8];
        float tm[2] = {-1e30f, -1e30f};

        #pragma unroll
        for (int kk = 0; kk < 8; ++kk){
            const int j = kk*8 + jl;
            const float* krow = kb + j*KPAD + qsec*32;
            ull b0[2], b1[2];
            b0[0]=b0[1]=b1[0]=b1[1]=pack2(0.f, 0.f);
            #pragma unroll
            for (int r = 0; r < 8; ++r){
                ulonglong2 kv = *reinterpret_cast<const ulonglong2*>(krow + 4*r);
                #pragma unroll
                for (int qi = 0; qi < 2; ++qi){
                    b0[qi] = f2fma(kv.x, qr[qi][r].x, b0[qi]);
                    b1[qi] = f2fma(kv.y, qr[qi][r].y, b1[qi]);
                }
            }
            #pragma unroll
            for (int qi = 0; qi < 2; ++qi){
                float2 s0 = unpack2(b0[qi]);
                float2 s1 = unpack2(b1[qi]);
                float dot = (s0.x + s0.y) + (s1.x + s1.y);
                dot += __shfl_xor_sync(0xffffffffu, dot, 8);   // combine d-sections
                dot += __shfl_xor_sync(0xffffffffu, dot, 16);
                float sc = dot * SCALE;
                if (base + j >= ktot) sc = -1e30f;
                p[qi][kk] = sc;
                tm[qi] = fmaxf(tm[qi], sc);
            }
        }

        // ---- online softmax update
        #pragma unroll
        for (int qi = 0; qi < 2; ++qi){
            float v0 = tm[qi];
            v0 = fmaxf(v0, __shfl_xor_sync(0xffffffffu, v0, 1));
            v0 = fmaxf(v0, __shfl_xor_sync(0xffffffffu, v0, 2));
            v0 = fmaxf(v0, __shfl_xor_sync(0xffffffffu, v0, 4));
            float mnew = fmaxf(m[qi], v0);
            float corr = __expf(m[qi] - mnew);
            m[qi] = mnew;
            float ps = 0.f;
            #pragma unroll
            for (int kk = 0; kk < 8; ++kk){
                float e = __expf(p[qi][kk] - mnew);
                p[qi][kk] = e;
                ps += e;
            }
            ps += __shfl_xor_sync(0xffffffffu, ps, 1);
            ps += __shfl_xor_sync(0xffffffffu, ps, 2);
            ps += __shfl_xor_sync(0xffffffffu, ps, 4);
            lsum[qi] = lsum[qi]*corr + ps;
            ull c2 = pack2(corr, corr);
            a01[qi] = f2mul(a01[qi], c2);
            a23[qi] = f2mul(a23[qi], c2);
        }

        // ---- PV: lane owns dims lane*4..lane*4+3, probs broadcast via shfl
        const float* vrow = vb + lane*4;
        #pragma unroll
        for (int j = 0; j < TT; ++j){
            ulonglong2 vv = *reinterpret_cast<const ulonglong2*>(vrow + j*D_);
            #pragma unroll
            for (int qi = 0; qi < 2; ++qi){
                float pj = __shfl_sync(0xffffffffu, p[qi][j>>3], j & 7);
                ull p2 = pack2(pj, pj);
                a01[qi] = f2fma(vv.x, p2, a01[qi]);
                a23[qi] = f2fma(vv.y, p2, a23[qi]);
            }
        }
        __syncthreads();   // protect buffer before next prefetch overwrites it
    }

    // ---- epilogue: out[b][q][h*128 + d]
    #pragma unroll
    for (int qi = 0; qi < 2; ++qi){
        float inv = 1.0f / lsum[qi];
        float2 o0 = unpack2(a01[qi]);
        float2 o1 = unpack2(a23[qi]);
        float4 o = make_float4(o0.x*inv, o0.y*inv, o1.x*inv, o1.y*inv);
        float* op = outg + (size_t)(b*SQ_ + q0 + qi)*(H_*D_) + h*D_ + lane*4;
        *reinterpret_cast<float4*>(op) = o;
    }
}

extern "C" void kernel_launch(void* const* d_in, const int* in_sizes, int n_in,
                              void* d_out, int out_size)
{
    const float* q  = (const float*)d_in[0];
    const float* k  = (const float*)d_in[1];
    const float* v  = (const float*)d_in[2];
    const float* kc = (const float*)d_in[3];
    const float* vc = (const float*)d_in[4];
    const int* sidx = (const int*)d_in[5];

    const size_t smem_bytes = (size_t)(2*TT*KPAD + 2*TT*D_) * sizeof(float);  // 133120
    cudaFuncSetAttribute((const void*)attn_kernel,
                         cudaFuncAttributeMaxDynamicSharedMemorySize,
                         (int)smem_bytes);

    attn_kernel<<<B_*H_, NTHREADS, smem_bytes>>>(q, k, v, kc, vc, sidx, (float*)d_out);
}